// round 1
// baseline (speedup 1.0000x reference)
#include <cuda_runtime.h>
#include <math.h>

#define NROWS 131072
#define DDIM  64
#define KCODE 512
#define KS    516    // sBT row stride (floats): 512 + 4 pad, keeps 16B alignment
#define AS    132    // sAT row stride (floats): 128 + 4 pad

// dynamic smem for k_main (floats):
// sBT 64*516 + sAT 64*132 + sEn 512 + rMin 2048 + rIdx 2048 + sIdx 128 + sXn 128
#define MAIN_SMEM_FLOATS (64 * KS + 64 * AS + KCODE + 2048 + 2048 + 128 + 128)

// ---- scratch (static device globals; no allocation allowed) ----
__device__ float g_dw[KCODE * DDIM];
__device__ int   g_counts[KCODE];
__device__ float g_enorm[KCODE];
__device__ float g_embT[DDIM * KCODE];          // codebook transposed [d][k]
__device__ float g_inT[(size_t)DDIM * NROWS];   // inputs transposed [d][n] (33.5 MB)
__device__ float g_new_emb[KCODE * DDIM];
__device__ int   g_idx[NROWS];
__device__ float g_loss;

// ---------------------------------------------------------------------------
// k_init: zero dw/counts/loss, compute codebook norms, transpose codebook.
// grid 64 x 512
// ---------------------------------------------------------------------------
__global__ void k_init(const float* __restrict__ emb)
{
    const int gid = blockIdx.x * 512 + threadIdx.x;   // 0..32767
    g_dw[gid] = 0.0f;
    const int d = gid >> 9;
    const int k = gid & 511;
    g_embT[d * KCODE + k] = emb[k * DDIM + d];
    if (blockIdx.x == 0) {
        const int t = threadIdx.x;
        g_counts[t] = 0;
        const float4* e4 = (const float4*)(emb + t * DDIM);
        float s = 0.0f;
#pragma unroll
        for (int i = 0; i < 16; i++) {
            float4 v = e4[i];
            s += v.x * v.x + v.y * v.y + v.z * v.z + v.w * v.w;
        }
        g_enorm[t] = s;
        if (t == 0) g_loss = 0.0f;
    }
}

// ---------------------------------------------------------------------------
// k_trans: transpose inputs [N][64] -> g_inT [64][N], both sides coalesced.
// grid NROWS/64 x 256
// ---------------------------------------------------------------------------
__global__ __launch_bounds__(256) void k_trans(const float* __restrict__ x)
{
    __shared__ float s[64][65];
    const int t = threadIdx.x;
    const int n0 = blockIdx.x * 64;
    const float4* x4 = (const float4*)(x + (size_t)n0 * DDIM);
#pragma unroll
    for (int it = 0; it < 4; it++) {
        int i = it * 256 + t;          // 1024 float4 total
        int r = i >> 4;
        int c = (i & 15) << 2;
        float4 v = x4[i];
        s[r][c] = v.x; s[r][c + 1] = v.y; s[r][c + 2] = v.z; s[r][c + 3] = v.w;
    }
    __syncthreads();
#pragma unroll
    for (int it = 0; it < 16; it++) {
        int i = it * 256 + t;          // 4096 scalars
        int d = i >> 6;
        int n = i & 63;
        g_inT[(size_t)d * NROWS + n0 + n] = s[n][d];
    }
}

// ---------------------------------------------------------------------------
// k_main: distances + argmin + encodings scatter + counts + dw atomics.
// grid NROWS/128 x 256, dynamic smem MAIN_SMEM_FLOATS*4 bytes.
// Microtile: thread (ty,tx) = (tid/16, tid%16) owns rows ty*8..+7,
// codes {kk*128 + tx*8..+7} for kk=0..3. 8x8 fp32 register tile.
// ---------------------------------------------------------------------------
__global__ __launch_bounds__(256, 1) void k_main(const float* __restrict__ flat,
                                                 float* __restrict__ enc)
{
    extern __shared__ __align__(16) float sm[];
    float* sBT  = sm;                       // [64][KS]
    float* sAT  = sBT + 64 * KS;            // [64][AS]
    float* sEn  = sAT + 64 * AS;            // [512]
    float* rMin = sEn + KCODE;              // [256*8]
    int*   rIdx = (int*)(rMin + 2048);      // [256*8]
    int*   sIdx = rIdx + 2048;              // [128]
    float* sXn  = (float*)(sIdx + 128);     // [128]

    const int tid = threadIdx.x;
    const int n0  = blockIdx.x * 128;

    // codebook: gmem already transposed -> linear float4 fill, conflict-free
    {
        const float4* src = (const float4*)g_embT;
#pragma unroll
        for (int it = 0; it < 32; it++) {
            int i = it * 256 + tid;          // 8192 float4
            int d = i >> 7;
            int k4 = i & 127;
            float4 v = src[i];
            *(float4*)(sBT + d * KS + (k4 << 2)) = v;
        }
    }
    // A tile from transposed inputs -> linear float4 fill, conflict-free
    {
#pragma unroll
        for (int it = 0; it < 8; it++) {
            int i = it * 256 + tid;          // 2048 float4
            int d = i >> 5;
            int r4 = i & 31;
            float4 v = *(const float4*)(g_inT + (size_t)d * NROWS + n0 + (r4 << 2));
            *(float4*)(sAT + d * AS + (r4 << 2)) = v;
        }
    }
    for (int i = tid; i < KCODE; i += 256) sEn[i] = g_enorm[i];
    __syncthreads();

    // per-row ||x||^2 (needed to mimic reference rounding association)
    if (tid < 128) {
        float s = 0.0f;
#pragma unroll
        for (int d = 0; d < 64; d++) {
            float a = sAT[d * AS + tid];
            s = fmaf(a, a, s);
        }
        sXn[tid] = s;
    }
    __syncthreads();

    const int ty = tid >> 4;
    const int tx = tid & 15;
    const float* aB = sAT + (ty << 3);

    float xn[8];
#pragma unroll
    for (int r = 0; r < 8; r++) xn[r] = sXn[(ty << 3) + r];

    float mn[8];
    int   mi[8];
#pragma unroll
    for (int r = 0; r < 8; r++) { mn[r] = 3.402823466e38f; mi[r] = 0x7fffffff; }

    for (int kk = 0; kk < 4; kk++) {
        const float* bB = sBT + kk * 128 + (tx << 3);
        float acc[8][8];
#pragma unroll
        for (int r = 0; r < 8; r++)
#pragma unroll
            for (int c = 0; c < 8; c++) acc[r][c] = 0.0f;

#pragma unroll 4
        for (int d = 0; d < 64; d++) {
            float4 a0 = *(const float4*)(aB + d * AS);
            float4 a1 = *(const float4*)(aB + d * AS + 4);
            float4 b0 = *(const float4*)(bB + d * KS);
            float4 b1 = *(const float4*)(bB + d * KS + 4);
            float av[8] = {a0.x, a0.y, a0.z, a0.w, a1.x, a1.y, a1.z, a1.w};
            float bv[8] = {b0.x, b0.y, b0.z, b0.w, b1.x, b1.y, b1.z, b1.w};
#pragma unroll
            for (int r = 0; r < 8; r++)
#pragma unroll
                for (int c = 0; c < 8; c++)
                    acc[r][c] = fmaf(av[r], bv[c], acc[r][c]);
        }

#pragma unroll
        for (int c = 0; c < 8; c++) {
            int code = kk * 128 + (tx << 3) + c;
            float en = sEn[code];
#pragma unroll
            for (int r = 0; r < 8; r++) {
                // match reference association: (xx - 2*dot) + ||e||^2, no contraction
                float t1 = __fmul_rn(2.0f, acc[r][c]);
                float t2 = __fsub_rn(xn[r], t1);
                float s  = __fadd_rn(t2, en);
                if (s < mn[r] || (s == mn[r] && code < mi[r])) { mn[r] = s; mi[r] = code; }
            }
        }
    }

    // cross-thread argmin reduction (16 tx threads share each row)
#pragma unroll
    for (int r = 0; r < 8; r++) { rMin[tid * 8 + r] = mn[r]; rIdx[tid * 8 + r] = mi[r]; }
    __syncthreads();

    if (tid < 128) {
        const int row = tid;
        const int tyr = row >> 3;
        const int rr  = row & 7;
        float bm = 3.402823466e38f;
        int   bi = 0x7fffffff;
        for (int x = 0; x < 16; x++) {
            int src = ((tyr << 4) + x) * 8 + rr;
            float v = rMin[src];
            int  id = rIdx[src];
            if (v < bm || (v == bm && id < bi)) { bm = v; bi = id; }
        }
        g_idx[n0 + row] = bi;
        sIdx[row] = bi;
        enc[(size_t)(n0 + row) * KCODE + bi] = 1.0f;   // rest zeroed by memset
        atomicAdd(&g_counts[bi], 1);
    }
    __syncthreads();

    // dw segment-sum scatter (coalesced gmem read, fp atomics)
    const float* rowsG = flat + (size_t)n0 * DDIM;
#pragma unroll
    for (int it = 0; it < 32; it++) {
        int i = it * 256 + tid;            // 8192 elements
        int r = i >> 6;
        int d = i & 63;
        atomicAdd(&g_dw[sIdx[r] * DDIM + d], rowsG[i]);
    }
}

// ---------------------------------------------------------------------------
// k_update: EMA + Laplace smoothing + new codebook + perplexity. 1 x 512.
// ---------------------------------------------------------------------------
__global__ void k_update(const float* __restrict__ ema_cs,
                         const float* __restrict__ ema_w,
                         float* __restrict__ outP)
{
    __shared__ float red[512];
    const int t = threadIdx.x;
    float c  = (float)g_counts[t];
    float cs = ema_cs[t] * 0.99f + 0.01f * c;
    red[t] = cs;
    __syncthreads();
    for (int s = 256; s > 0; s >>= 1) {
        if (t < s) red[t] += red[t + s];
        __syncthreads();
    }
    float nsum = red[0];
    __syncthreads();
    float csS = (cs + 1e-5f) / (nsum + 512.0f * 1e-5f) * nsum;
#pragma unroll
    for (int d = 0; d < 64; d++) {
        float w = ema_w[t * 64 + d] * 0.99f + 0.01f * g_dw[t * 64 + d];
        g_new_emb[t * 64 + d] = w / csS;
    }
    // perplexity
    float p = c * (1.0f / 131072.0f);
    float e = p * logf(p + 1e-10f);
    red[t] = e;
    __syncthreads();
    for (int s = 256; s > 0; s >>= 1) {
        if (t < s) red[t] += red[t + s];
        __syncthreads();
    }
    if (t == 0) outP[0] = expf(-red[0]);
}

// ---------------------------------------------------------------------------
// k_quant: gather updated codebook, NHWC->NCHW transposed write, loss partial.
// grid NROWS/64 x 256
// ---------------------------------------------------------------------------
__global__ __launch_bounds__(256) void k_quant(const float* __restrict__ x,
                                               float* __restrict__ outQ)
{
    __shared__ float q[64][65];
    __shared__ int   idxs[64];
    __shared__ float wsum[8];
    const int t  = threadIdx.x;
    const int n0 = blockIdx.x * 64;
    if (t < 64) idxs[t] = g_idx[n0 + t];
    __syncthreads();

    float lsum = 0.0f;
    const float* xb = x + (size_t)n0 * DDIM;
#pragma unroll
    for (int it = 0; it < 16; it++) {
        int i = it * 256 + t;
        int r = i >> 6;
        int d = i & 63;
        float qv = g_new_emb[idxs[r] * DDIM + d];
        float xv = xb[i];
        float df = qv - xv;
        lsum = fmaf(df, df, lsum);
        q[r][d] = qv;
    }
    __syncthreads();

    const int b   = n0 >> 12;       // batch index (4096 rows per image)
    const int loc = n0 & 4095;
    float* base = outQ + (size_t)b * 262144 + loc;
#pragma unroll
    for (int it = 0; it < 16; it++) {
        int i = it * 256 + t;
        int d = i >> 6;
        int n = i & 63;
        base[d * 4096 + n] = q[n][d];   // coalesced: 64 consecutive n per d
    }

#pragma unroll
    for (int o = 16; o > 0; o >>= 1) lsum += __shfl_xor_sync(0xffffffffu, lsum, o);
    if ((t & 31) == 0) wsum[t >> 5] = lsum;
    __syncthreads();
    if (t == 0) {
        float s = 0.0f;
#pragma unroll
        for (int w = 0; w < 8; w++) s += wsum[w];
        atomicAdd(&g_loss, s);
    }
}

__global__ void k_final(float* __restrict__ out0)
{
    out0[0] = 0.25f * g_loss * (1.0f / 8388608.0f);  // mean over N*D = 2^23
}

// ---------------------------------------------------------------------------
// Output layout (return order, float32):
//   [0]                      loss
//   [1 .. 8388609)           quantized_st NCHW [32,64,64,64]
//   [8388609]                perplexity
//   [8388610 .. 75497474)    encodings [131072, 512]
// ---------------------------------------------------------------------------
extern "C" void kernel_launch(void* const* d_in, const int* in_sizes, int n_in,
                              void* d_out, int out_size)
{
    const float* inputs = (const float*)d_in[0];
    const float* emb_w  = (const float*)d_in[1];
    const float* ema_cs = (const float*)d_in[2];
    const float* ema_w  = (const float*)d_in[3];
    float* out  = (float*)d_out;
    float* outQ = out + 1;
    float* outP = out + 1 + 8388608;
    float* outE = out + 2 + 8388608;

    cudaFuncSetAttribute(k_main, cudaFuncAttributeMaxDynamicSharedMemorySize,
                         MAIN_SMEM_FLOATS * (int)sizeof(float));

    k_init<<<64, 512>>>(emb_w);
    k_trans<<<NROWS / 64, 256>>>(inputs);
    cudaMemsetAsync(outE, 0, (size_t)NROWS * KCODE * sizeof(float));
    k_main<<<NROWS / 128, 256, MAIN_SMEM_FLOATS * sizeof(float)>>>(inputs, outE);
    k_update<<<1, 512>>>(ema_cs, ema_w, outP);
    k_quant<<<NROWS / 64, 256>>>(inputs, outQ);
    k_final<<<1, 1>>>(out);
}

// round 4
// speedup vs baseline: 1.1104x; 1.1104x over previous
#include <cuda_runtime.h>
#include <math.h>
#include <stdint.h>

#define NROWS 131072
#define DDIM  64
#define KCODE 512

// ---- dynamic smem byte offsets for k_main ----
// A: 128 rows x 66 float2 (hi,lo) = 67584 B   (pad 66 to spread banks)
// B: 128 codes x 66 float2        = 67584 B
#define OFF_A   0
#define OFF_B   67584
#define OFF_EN  135168      // float[512]
#define OFF_XN  137216      // float[128]
#define OFF_IDX 137728      // int[128]
#define SMEM_DYN 138240

// ---- static device scratch ----
__device__ __align__(16) float2 g_B[KCODE * DDIM];  // codebook tf32 (hi,lo)
__device__ float  g_enorm[KCODE];
__device__ float  g_dw[KCODE * DDIM];
__device__ int    g_counts[KCODE];
__device__ float  g_csS[KCODE];
__device__ float  g_new_emb[KCODE * DDIM];
__device__ int    g_idx[NROWS];
__device__ float  g_loss;

// ---- helpers ----
__device__ __forceinline__ uint32_t f2tf(float a) {
    uint32_t r; asm("cvt.rna.tf32.f32 %0, %1;" : "=r"(r) : "f"(a)); return r;
}
__device__ __forceinline__ void mma8(float c[4], const uint32_t a[4],
                                     uint32_t b0, uint32_t b1) {
    asm volatile("mma.sync.aligned.m16n8k8.row.col.f32.tf32.tf32.f32 "
                 "{%0,%1,%2,%3}, {%4,%5,%6,%7}, {%8,%9}, {%0,%1,%2,%3};"
                 : "+f"(c[0]), "+f"(c[1]), "+f"(c[2]), "+f"(c[3])
                 : "r"(a[0]), "r"(a[1]), "r"(a[2]), "r"(a[3]),
                   "r"(b0), "r"(b1));
}

// ---------------------------------------------------------------------------
// k_init: split codebook fp32 -> tf32 (hi,lo) pairs, norms, zero scratch.
// grid 64 x 512 (one thread per codebook element)
// ---------------------------------------------------------------------------
__global__ void k_init(const float* __restrict__ emb)
{
    const int t = threadIdx.x;
    const int gid = blockIdx.x * 512 + t;
    float a = emb[gid];
    uint32_t hb = f2tf(a);
    float hf = __uint_as_float(hb);
    uint32_t lb = f2tf(a - hf);
    g_B[gid] = make_float2(hf, __uint_as_float(lb));
    g_dw[gid] = 0.0f;
    if (blockIdx.x == 0) {
        g_counts[t] = 0;
        const float4* e4 = (const float4*)(emb + t * DDIM);
        float s = 0.0f;
#pragma unroll
        for (int i = 0; i < 16; i++) {
            float4 v = e4[i];
            s += v.x * v.x + v.y * v.y + v.z * v.z + v.w * v.w;
        }
        g_enorm[t] = s;
        if (t == 0) g_loss = 0.0f;
    }
}

// ---------------------------------------------------------------------------
// k_main: double-tf32 mma.sync distances + argmin + fused one-hot + dw.
// grid 1024 x 256. Block tile: 128 rows x 512 codes, K = 64.
// Warp w owns rows w*16 .. w*16+15 (mma m16), loops all 512 codes.
// ---------------------------------------------------------------------------
__global__ void __launch_bounds__(256, 1) k_main(const float* __restrict__ flat,
                                                 float* __restrict__ enc)
{
    extern __shared__ __align__(16) unsigned char smx[];
    float* sEn  = (float*)(smx + OFF_EN);
    float* sXn  = (float*)(smx + OFF_XN);
    int*   sIdx = (int*)(smx + OFF_IDX);

    const int tid  = threadIdx.x;
    const int lane = tid & 31;
    const int w    = tid >> 5;
    const int n0   = blockIdx.x * 128;

    // ---- A fill: fp32 -> (hi,lo) tf32 pairs in smem; row norms ----
    {
        const float2* f2 = (const float2*)(flat + (size_t)n0 * DDIM);
#pragma unroll
        for (int it = 0; it < 16; it++) {
            int i = it * 256 + tid;          // 4096 float2 (128 rows x 32)
            int row = i >> 5, j = i & 31;
            float2 a = f2[i];
            uint32_t hx = f2tf(a.x); float hxf = __uint_as_float(hx);
            uint32_t lx = f2tf(a.x - hxf);
            uint32_t hy = f2tf(a.y); float hyf = __uint_as_float(hy);
            uint32_t ly = f2tf(a.y - hyf);
            float4 st;
            st.x = hxf; st.y = __uint_as_float(lx);
            st.z = hyf; st.w = __uint_as_float(ly);
            *(float4*)(smx + OFF_A + ((size_t)row * 66 + j * 2) * 8) = st;
            float sq = fmaf(a.x, a.x, a.y * a.y);
#pragma unroll
            for (int o = 16; o; o >>= 1) sq += __shfl_xor_sync(0xffffffffu, sq, o);
            if (lane == 0) sXn[row] = sq;    // row == it*8 + w for this warp
        }
    }
    for (int i = tid; i < KCODE; i += 256) sEn[i] = g_enorm[i];
    __syncthreads();

    // ---- A fragment preload (register-resident for whole kernel) ----
    const int r0 = w * 16 + (lane >> 2);
    uint32_t ah[8][4], al[8][4];
#pragma unroll
    for (int ks = 0; ks < 8; ks++) {
        int k0 = ks * 8 + (lane & 3);
        float2 v;
        v = *(const float2*)(smx + OFF_A + ((size_t)r0 * 66 + k0) * 8);
        ah[ks][0] = __float_as_uint(v.x); al[ks][0] = __float_as_uint(v.y);
        v = *(const float2*)(smx + OFF_A + ((size_t)(r0 + 8) * 66 + k0) * 8);
        ah[ks][1] = __float_as_uint(v.x); al[ks][1] = __float_as_uint(v.y);
        v = *(const float2*)(smx + OFF_A + ((size_t)r0 * 66 + k0 + 4) * 8);
        ah[ks][2] = __float_as_uint(v.x); al[ks][2] = __float_as_uint(v.y);
        v = *(const float2*)(smx + OFF_A + ((size_t)(r0 + 8) * 66 + k0 + 4) * 8);
        ah[ks][3] = __float_as_uint(v.x); al[ks][3] = __float_as_uint(v.y);
    }
    const float xn0 = sXn[r0];
    const float xn1 = sXn[r0 + 8];
    float mn0 = 3.402823466e38f, mn1 = 3.402823466e38f;
    int   mi0 = 0, mi1 = 0;

    // ---- main loop: 4 chunks of 128 codes ----
#pragma unroll 1
    for (int c = 0; c < 4; c++) {
        // B chunk fill: linear float4 copy of pre-split pairs
        {
            const float4* src = ((const float4*)g_B) + (size_t)c * 128 * 32;
#pragma unroll
            for (int it = 0; it < 16; it++) {
                int i = it * 256 + tid;       // 4096 float4
                int code = i >> 5, j = i & 31;
                *(float4*)(smx + OFF_B + ((size_t)code * 66 + j * 2) * 8) = src[i];
            }
        }
        __syncthreads();

#pragma unroll 1
        for (int pr = 0; pr < 8; pr++) {      // 8 pairs of 8-code tiles
            float acc[2][4][4];
#pragma unroll
            for (int t2 = 0; t2 < 2; t2++)
#pragma unroll
                for (int p = 0; p < 4; p++)
#pragma unroll
                    for (int i = 0; i < 4; i++) acc[t2][p][i] = 0.0f;

#pragma unroll
            for (int ks = 0; ks < 8; ks++) {
#pragma unroll
                for (int t2 = 0; t2 < 2; t2++) {
                    int col = pr * 16 + t2 * 8 + (lane >> 2);
                    int kk = ks * 8 + (lane & 3);
                    float2 b0 = *(const float2*)(smx + OFF_B + ((size_t)col * 66 + kk) * 8);
                    float2 b1 = *(const float2*)(smx + OFF_B + ((size_t)col * 66 + kk + 4) * 8);
                    uint32_t bh0 = __float_as_uint(b0.x), bl0 = __float_as_uint(b0.y);
                    uint32_t bh1 = __float_as_uint(b1.x), bl1 = __float_as_uint(b1.y);
                    mma8(acc[t2][0], ah[ks], bh0, bh1);   // hi*hi
                    mma8(acc[t2][1], ah[ks], bl0, bl1);   // hi*lo
                    mma8(acc[t2][2], al[ks], bh0, bh1);   // lo*hi
                    mma8(acc[t2][3], al[ks], bl0, bl1);   // lo*lo
                }
            }

            // epilogue: fold into running argmin (ascending col order per row)
#pragma unroll
            for (int t2 = 0; t2 < 2; t2++) {
                int cb = c * 128 + pr * 16 + t2 * 8 + (lane & 3) * 2;
#pragma unroll
                for (int i = 0; i < 4; i++) {
                    float dot = ((acc[t2][0][i] + acc[t2][1][i]) + acc[t2][2][i]) + acc[t2][3][i];
                    int col = cb + (i & 1);
                    float xn = (i < 2) ? xn0 : xn1;
                    float s = __fadd_rn(__fsub_rn(xn, __fmul_rn(2.0f, dot)), sEn[col]);
                    if (i < 2) { if (s < mn0) { mn0 = s; mi0 = col; } }
                    else       { if (s < mn1) { mn1 = s; mi1 = col; } }
                }
            }
        }
        __syncthreads();   // done reading this B chunk
    }

    // ---- cross-lane argmin reduce (4 threads share each row) ----
#pragma unroll
    for (int off = 1; off < 4; off <<= 1) {
        float om = __shfl_xor_sync(0xffffffffu, mn0, off);
        int   oi = __shfl_xor_sync(0xffffffffu, mi0, off);
        if (om < mn0 || (om == mn0 && oi < mi0)) { mn0 = om; mi0 = oi; }
        om = __shfl_xor_sync(0xffffffffu, mn1, off);
        oi = __shfl_xor_sync(0xffffffffu, mi1, off);
        if (om < mn1 || (om == mn1 && oi < mi1)) { mn1 = om; mi1 = oi; }
    }
    if ((lane & 3) == 0) {
        g_idx[n0 + r0] = mi0;     sIdx[r0] = mi0;
        g_idx[n0 + r0 + 8] = mi1; sIdx[r0 + 8] = mi1;
        atomicAdd(&g_counts[mi0], 1);
        atomicAdd(&g_counts[mi1], 1);
    }
    __syncthreads();

    // ---- fused encodings write: zeros + one-hot (float2: base is 8B-aligned) ----
    {
        float2* eb = (float2*)(enc + (size_t)n0 * KCODE);
#pragma unroll 4
        for (int it = 0; it < 128; it++) {
            int i = it * 256 + tid;          // 32768 float2 = 128 rows x 256
            int row = i >> 8, f = i & 255;
            int hot = sIdx[row];
            int base = f << 1;
            float2 v;
            v.x = (hot == base)     ? 1.0f : 0.0f;
            v.y = (hot == base + 1) ? 1.0f : 0.0f;
            eb[i] = v;
        }
    }

    // ---- dw segment-sum scatter (coalesced reads, fp atomics) ----
    {
        const float* rowsG = flat + (size_t)n0 * DDIM;
#pragma unroll 4
        for (int it = 0; it < 32; it++) {
            int i = it * 256 + tid;          // 8192 elements
            int r = i >> 6, d = i & 63;
            atomicAdd(&g_dw[sIdx[r] * DDIM + d], rowsG[i]);
        }
    }
}

// ---------------------------------------------------------------------------
// k_update_cs: counts -> smoothed cluster sizes + perplexity. 1 x 512.
// ---------------------------------------------------------------------------
__global__ void k_update_cs(const float* __restrict__ ema_cs, float* __restrict__ outP)
{
    __shared__ float red[512];
    const int t = threadIdx.x;
    float c  = (float)g_counts[t];
    float cs = ema_cs[t] * 0.99f + 0.01f * c;
    red[t] = cs;
    __syncthreads();
    for (int s = 256; s; s >>= 1) { if (t < s) red[t] += red[t + s]; __syncthreads(); }
    float nsum = red[0];
    __syncthreads();
    g_csS[t] = (cs + 1e-5f) / (nsum + 512.0f * 1e-5f) * nsum;

    float p = c * (1.0f / 131072.0f);
    red[t] = p * logf(p + 1e-10f);
    __syncthreads();
    for (int s = 256; s; s >>= 1) { if (t < s) red[t] += red[t + s]; __syncthreads(); }
    if (t == 0) outP[0] = expf(-red[0]);
}

// k_update_emb: parallel codebook update. grid 64 x 512.
__global__ void k_update_emb(const float* __restrict__ ema_w)
{
    const int gid = blockIdx.x * 512 + threadIdx.x;  // 32768
    const int k = gid >> 6;
    float w = ema_w[gid] * 0.99f + 0.01f * g_dw[gid];
    g_new_emb[gid] = w / g_csS[k];
}

// ---------------------------------------------------------------------------
// k_quant: gather updated codebook, NHWC->NCHW write, loss partial.
// grid NROWS/64 x 256
// ---------------------------------------------------------------------------
__global__ __launch_bounds__(256) void k_quant(const float* __restrict__ x,
                                               float* __restrict__ outQ)
{
    __shared__ float q[64][65];
    __shared__ int   idxs[64];
    __shared__ float wsum[8];
    const int t  = threadIdx.x;
    const int n0 = blockIdx.x * 64;
    if (t < 64) idxs[t] = g_idx[n0 + t];
    __syncthreads();

    float lsum = 0.0f;
    const float* xb = x + (size_t)n0 * DDIM;
#pragma unroll
    for (int it = 0; it < 16; it++) {
        int i = it * 256 + t;
        int r = i >> 6, d = i & 63;
        float qv = g_new_emb[idxs[r] * DDIM + d];
        float xv = xb[i];
        float df = qv - xv;
        lsum = fmaf(df, df, lsum);
        q[r][d] = qv;
    }
    __syncthreads();

    const int b   = n0 >> 12;
    const int loc = n0 & 4095;
    float* dst = outQ + (size_t)b * 262144 + loc;
#pragma unroll
    for (int it = 0; it < 16; it++) {
        int i = it * 256 + t;
        int d = i >> 6, n = i & 63;
        dst[d * 4096 + n] = q[n][d];
    }

#pragma unroll
    for (int o = 16; o; o >>= 1) lsum += __shfl_xor_sync(0xffffffffu, lsum, o);
    if ((t & 31) == 0) wsum[t >> 5] = lsum;
    __syncthreads();
    if (t == 0) {
        float s = 0.0f;
#pragma unroll
        for (int wv = 0; wv < 8; wv++) s += wsum[wv];
        atomicAdd(&g_loss, s);
    }
}

__global__ void k_final(float* __restrict__ out0)
{
    out0[0] = 0.25f * g_loss * (1.0f / 8388608.0f);
}

// ---------------------------------------------------------------------------
// Output layout (float32): [0] loss | [1..8388609) quantized NCHW |
// [8388609] perplexity | [8388610..) encodings [131072, 512]
// ---------------------------------------------------------------------------
extern "C" void kernel_launch(void* const* d_in, const int* in_sizes, int n_in,
                              void* d_out, int out_size)
{
    const float* inputs = (const float*)d_in[0];
    const float* emb_w  = (const float*)d_in[1];
    const float* ema_cs = (const float*)d_in[2];
    const float* ema_w  = (const float*)d_in[3];
    float* out  = (float*)d_out;
    float* outQ = out + 1;
    float* outP = out + 1 + 8388608;
    float* outE = out + 2 + 8388608;

    cudaFuncSetAttribute(k_main, cudaFuncAttributeMaxDynamicSharedMemorySize, SMEM_DYN);

    k_init<<<64, 512>>>(emb_w);
    k_main<<<NROWS / 128, 256, SMEM_DYN>>>(inputs, outE);
    k_update_cs<<<1, 512>>>(ema_cs, outP);
    k_update_emb<<<64, 512>>>(ema_w);
    k_quant<<<NROWS / 64, 256>>>(inputs, outQ);
    k_final<<<1, 1>>>(out);
}

// round 5
// speedup vs baseline: 1.9934x; 1.7953x over previous
#include <cuda_runtime.h>
#include <cuda_fp16.h>
#include <math.h>
#include <stdint.h>

#define NROWS 131072
#define DDIM  64
#define KCODE 512

// ---- dynamic smem byte offsets for k_main ----
// planes padded to 72 halves (144 B) per row -> 4-bank shift per row/col
#define OFF_AH  0           // 128 rows x 144B
#define OFF_AL  18432
#define OFF_BH  36864       // 128 codes x 144B (one chunk)
#define OFF_BL  55296
#define OFF_EN  73728       // float[512]
#define OFF_XN  75776       // float[128]
#define OFF_IDX 76288       // int[128]
#define SMEM_DYN 76800

// ---- static device scratch ----
__device__ __align__(16) __half g_Bh[KCODE * DDIM];   // codebook hi plane
__device__ __align__(16) __half g_Bl[KCODE * DDIM];   // codebook lo' plane
__device__ float  g_enorm[KCODE];
__device__ float  g_dw[KCODE * DDIM];
__device__ int    g_counts[KCODE];
__device__ float  g_csS[KCODE];
__device__ float  g_new_emb[KCODE * DDIM];
__device__ int    g_idx[NROWS];
__device__ float  g_loss;

// ---- helpers ----
__device__ __forceinline__ void split2h(float a, __half& hi, __half& lo) {
    hi = __float2half_rn(a);
    float r = a - __half2float(hi);      // exact
    lo = __float2half_rn(r * 2048.0f);   // scaled residual, avoids subnormals
}
__device__ __forceinline__ void mma16(float c[4], const uint32_t a[4],
                                      uint32_t b0, uint32_t b1) {
    asm volatile("mma.sync.aligned.m16n8k16.row.col.f32.f16.f16.f32 "
                 "{%0,%1,%2,%3}, {%4,%5,%6,%7}, {%8,%9}, {%0,%1,%2,%3};"
                 : "+f"(c[0]), "+f"(c[1]), "+f"(c[2]), "+f"(c[3])
                 : "r"(a[0]), "r"(a[1]), "r"(a[2]), "r"(a[3]),
                   "r"(b0), "r"(b1));
}

// ---------------------------------------------------------------------------
// k_init: split codebook fp32 -> fp16 (hi, lo') planes, norms, zero scratch.
// grid 64 x 512 (one thread per codebook element)
// ---------------------------------------------------------------------------
__global__ void k_init(const float* __restrict__ emb)
{
    const int t = threadIdx.x;
    const int gid = blockIdx.x * 512 + t;
    float a = emb[gid];
    __half hi, lo;
    split2h(a, hi, lo);
    g_Bh[gid] = hi;
    g_Bl[gid] = lo;
    g_dw[gid] = 0.0f;
    if (blockIdx.x == 0) {
        g_counts[t] = 0;
        const float4* e4 = (const float4*)(emb + t * DDIM);
        float s = 0.0f;
#pragma unroll
        for (int i = 0; i < 16; i++) {
            float4 v = e4[i];
            s += v.x * v.x + v.y * v.y + v.z * v.z + v.w * v.w;
        }
        g_enorm[t] = s;
        if (t == 0) g_loss = 0.0f;
    }
}

// ---------------------------------------------------------------------------
// k_main: double-fp16 m16n8k16 distances + argmin + fused one-hot + dw.
// grid 1024 x 256, 2 blocks/SM. Block tile: 128 rows x 512 codes, K = 64.
// Warp w owns rows w*16 .. w*16+15.
// ---------------------------------------------------------------------------
__global__ void __launch_bounds__(256, 2) k_main(const float* __restrict__ flat,
                                                 float* __restrict__ enc)
{
    extern __shared__ __align__(16) unsigned char smx[];
    float* sEn  = (float*)(smx + OFF_EN);
    float* sXn  = (float*)(smx + OFF_XN);
    int*   sIdx = (int*)(smx + OFF_IDX);

    const int tid  = threadIdx.x;
    const int lane = tid & 31;
    const int w    = tid >> 5;
    const int n0   = blockIdx.x * 128;

    // ---- A fill: fp32 -> (hi, lo') fp16 planes; row norms ----
    {
        const float2* f2 = (const float2*)(flat + (size_t)n0 * DDIM);
#pragma unroll
        for (int it = 0; it < 16; it++) {
            int i = it * 256 + tid;          // 4096 half2-slots (128 rows x 32)
            int row = i >> 5, j = i & 31;
            float2 a = f2[i];
            __half hx, lx, hy, ly;
            split2h(a.x, hx, lx);
            split2h(a.y, hy, ly);
            __half2 h; h.x = hx; h.y = hy;
            *(__half2*)(smx + OFF_AH + row * 144 + j * 4) = h;
            h.x = lx; h.y = ly;
            *(__half2*)(smx + OFF_AL + row * 144 + j * 4) = h;
            float sq = fmaf(a.x, a.x, a.y * a.y);
#pragma unroll
            for (int o = 16; o; o >>= 1) sq += __shfl_xor_sync(0xffffffffu, sq, o);
            if (lane == 0) sXn[row] = sq;    // row == it*8 + w for this warp
        }
    }
    for (int i = tid; i < KCODE; i += 256) sEn[i] = g_enorm[i];
    __syncthreads();

    // ---- A fragment preload (register-resident): 4 k-steps of 16 ----
    const int r0 = w * 16 + (lane >> 2);
    uint32_t ah[4][4], al[4][4];
#pragma unroll
    for (int ks = 0; ks < 4; ks++) {
        int kb2 = (ks * 16 + (lane & 3) * 2) * 2;   // byte offset within row
        ah[ks][0] = *(const uint32_t*)(smx + OFF_AH + r0 * 144 + kb2);
        ah[ks][1] = *(const uint32_t*)(smx + OFF_AH + (r0 + 8) * 144 + kb2);
        ah[ks][2] = *(const uint32_t*)(smx + OFF_AH + r0 * 144 + kb2 + 16);
        ah[ks][3] = *(const uint32_t*)(smx + OFF_AH + (r0 + 8) * 144 + kb2 + 16);
        al[ks][0] = *(const uint32_t*)(smx + OFF_AL + r0 * 144 + kb2);
        al[ks][1] = *(const uint32_t*)(smx + OFF_AL + (r0 + 8) * 144 + kb2);
        al[ks][2] = *(const uint32_t*)(smx + OFF_AL + r0 * 144 + kb2 + 16);
        al[ks][3] = *(const uint32_t*)(smx + OFF_AL + (r0 + 8) * 144 + kb2 + 16);
    }
    const float xn0 = sXn[r0];
    const float xn1 = sXn[r0 + 8];
    float mn0 = 3.402823466e38f, mn1 = 3.402823466e38f;
    int   mi0 = 0, mi1 = 0;

    const float C1 = 4.8828125e-4f;          // 2^-11
    const float C2 = 2.384185791015625e-7f;  // 2^-22

    // ---- main loop: 4 chunks of 128 codes ----
#pragma unroll 1
    for (int c = 0; c < 4; c++) {
        // B chunk fill: 8B copies, padded stride 144B
        {
            const uint2* sh = (const uint2*)(g_Bh + (size_t)c * 128 * 64);
            const uint2* sl = (const uint2*)(g_Bl + (size_t)c * 128 * 64);
#pragma unroll
            for (int it = 0; it < 8; it++) {
                int i = it * 256 + tid;       // 2048 x 8B per plane
                int code = i >> 4, j = i & 15;
                *(uint2*)(smx + OFF_BH + code * 144 + j * 8) = sh[i];
                *(uint2*)(smx + OFF_BL + code * 144 + j * 8) = sl[i];
            }
        }
        __syncthreads();

#pragma unroll 1
        for (int pr = 0; pr < 8; pr++) {      // 16 codes per pr
            float hh[2][4], mm[2][4], ll[2][4];
#pragma unroll
            for (int t2 = 0; t2 < 2; t2++)
#pragma unroll
                for (int i = 0; i < 4; i++) { hh[t2][i] = 0.0f; mm[t2][i] = 0.0f; ll[t2][i] = 0.0f; }

#pragma unroll
            for (int ks = 0; ks < 4; ks++) {
#pragma unroll
                for (int t2 = 0; t2 < 2; t2++) {
                    int col = pr * 16 + t2 * 8 + (lane >> 2);
                    int kb2 = (ks * 16 + (lane & 3) * 2) * 2;
                    uint32_t bh0 = *(const uint32_t*)(smx + OFF_BH + col * 144 + kb2);
                    uint32_t bh1 = *(const uint32_t*)(smx + OFF_BH + col * 144 + kb2 + 16);
                    uint32_t bl0 = *(const uint32_t*)(smx + OFF_BL + col * 144 + kb2);
                    uint32_t bl1 = *(const uint32_t*)(smx + OFF_BL + col * 144 + kb2 + 16);
                    mma16(hh[t2], ah[ks], bh0, bh1);   // hi*hi      (scale 1)
                    mma16(mm[t2], ah[ks], bl0, bl1);   // hi*lo'     (scale 2^-11)
                    mma16(mm[t2], al[ks], bh0, bh1);   // lo'*hi     (scale 2^-11)
                    mma16(ll[t2], al[ks], bl0, bl1);   // lo'*lo'    (scale 2^-22)
                }
            }

            // epilogue: fold into running argmin (ascending col order per row)
#pragma unroll
            for (int t2 = 0; t2 < 2; t2++) {
                int cb = c * 128 + pr * 16 + t2 * 8 + (lane & 3) * 2;
#pragma unroll
                for (int i = 0; i < 4; i++) {
                    float dot = fmaf(C2, ll[t2][i], fmaf(C1, mm[t2][i], hh[t2][i]));
                    int col = cb + (i & 1);
                    float xn = (i < 2) ? xn0 : xn1;
                    float s = __fadd_rn(__fsub_rn(xn, __fmul_rn(2.0f, dot)), sEn[col]);
                    if (i < 2) { if (s < mn0) { mn0 = s; mi0 = col; } }
                    else       { if (s < mn1) { mn1 = s; mi1 = col; } }
                }
            }
        }
        __syncthreads();   // done reading this B chunk
    }

    // ---- cross-lane argmin reduce (4 threads share each row) ----
#pragma unroll
    for (int off = 1; off < 4; off <<= 1) {
        float om = __shfl_xor_sync(0xffffffffu, mn0, off);
        int   oi = __shfl_xor_sync(0xffffffffu, mi0, off);
        if (om < mn0 || (om == mn0 && oi < mi0)) { mn0 = om; mi0 = oi; }
        om = __shfl_xor_sync(0xffffffffu, mn1, off);
        oi = __shfl_xor_sync(0xffffffffu, mi1, off);
        if (om < mn1 || (om == mn1 && oi < mi1)) { mn1 = om; mi1 = oi; }
    }
    if ((lane & 3) == 0) {
        g_idx[n0 + r0] = mi0;     sIdx[r0] = mi0;
        g_idx[n0 + r0 + 8] = mi1; sIdx[r0 + 8] = mi1;
        atomicAdd(&g_counts[mi0], 1);
        atomicAdd(&g_counts[mi1], 1);
    }
    __syncthreads();

    // ---- fused encodings write: zeros + one-hot (float2: base 8B-aligned) ----
    {
        float2* eb = (float2*)(enc + (size_t)n0 * KCODE);
#pragma unroll 4
        for (int it = 0; it < 128; it++) {
            int i = it * 256 + tid;          // 32768 float2 = 128 rows x 256
            int row = i >> 8, f = i & 255;
            int hot = sIdx[row];
            int base = f << 1;
            float2 v;
            v.x = (hot == base)     ? 1.0f : 0.0f;
            v.y = (hot == base + 1) ? 1.0f : 0.0f;
            eb[i] = v;
        }
    }

    // ---- dw segment-sum scatter (coalesced reads, fp atomics) ----
    {
        const float* rowsG = flat + (size_t)n0 * DDIM;
#pragma unroll 4
        for (int it = 0; it < 32; it++) {
            int i = it * 256 + tid;          // 8192 elements
            int r = i >> 6, d = i & 63;
            atomicAdd(&g_dw[sIdx[r] * DDIM + d], rowsG[i]);
        }
    }
}

// ---------------------------------------------------------------------------
// k_update_cs: counts -> smoothed cluster sizes + perplexity. 1 x 512.
// ---------------------------------------------------------------------------
__global__ void k_update_cs(const float* __restrict__ ema_cs, float* __restrict__ outP)
{
    __shared__ float red[512];
    const int t = threadIdx.x;
    float c  = (float)g_counts[t];
    float cs = ema_cs[t] * 0.99f + 0.01f * c;
    red[t] = cs;
    __syncthreads();
    for (int s = 256; s; s >>= 1) { if (t < s) red[t] += red[t + s]; __syncthreads(); }
    float nsum = red[0];
    __syncthreads();
    g_csS[t] = (cs + 1e-5f) / (nsum + 512.0f * 1e-5f) * nsum;

    float p = c * (1.0f / 131072.0f);
    red[t] = p * logf(p + 1e-10f);
    __syncthreads();
    for (int s = 256; s; s >>= 1) { if (t < s) red[t] += red[t + s]; __syncthreads(); }
    if (t == 0) outP[0] = expf(-red[0]);
}

// k_update_emb: parallel codebook update. grid 64 x 512.
__global__ void k_update_emb(const float* __restrict__ ema_w)
{
    const int gid = blockIdx.x * 512 + threadIdx.x;  // 32768
    const int k = gid >> 6;
    float w = ema_w[gid] * 0.99f + 0.01f * g_dw[gid];
    g_new_emb[gid] = w / g_csS[k];
}

// ---------------------------------------------------------------------------
// k_quant: gather updated codebook, NHWC->NCHW write, loss partial.
// grid NROWS/64 x 256
// ---------------------------------------------------------------------------
__global__ __launch_bounds__(256) void k_quant(const float* __restrict__ x,
                                               float* __restrict__ outQ)
{
    __shared__ float q[64][65];
    __shared__ int   idxs[64];
    __shared__ float wsum[8];
    const int t  = threadIdx.x;
    const int n0 = blockIdx.x * 64;
    if (t < 64) idxs[t] = g_idx[n0 + t];
    __syncthreads();

    float lsum = 0.0f;
    const float* xb = x + (size_t)n0 * DDIM;
#pragma unroll
    for (int it = 0; it < 16; it++) {
        int i = it * 256 + t;
        int r = i >> 6, d = i & 63;
        float qv = g_new_emb[idxs[r] * DDIM + d];
        float xv = xb[i];
        float df = qv - xv;
        lsum = fmaf(df, df, lsum);
        q[r][d] = qv;
    }
    __syncthreads();

    const int b   = n0 >> 12;
    const int loc = n0 & 4095;
    float* dst = outQ + (size_t)b * 262144 + loc;
#pragma unroll
    for (int it = 0; it < 16; it++) {
        int i = it * 256 + t;
        int d = i >> 6, n = i & 63;
        dst[d * 4096 + n] = q[n][d];
    }

#pragma unroll
    for (int o = 16; o; o >>= 1) lsum += __shfl_xor_sync(0xffffffffu, lsum, o);
    if ((t & 31) == 0) wsum[t >> 5] = lsum;
    __syncthreads();
    if (t == 0) {
        float s = 0.0f;
#pragma unroll
        for (int wv = 0; wv < 8; wv++) s += wsum[wv];
        atomicAdd(&g_loss, s);
    }
}

__global__ void k_final(float* __restrict__ out0)
{
    out0[0] = 0.25f * g_loss * (1.0f / 8388608.0f);
}

// ---------------------------------------------------------------------------
// Output layout (float32): [0] loss | [1..8388609) quantized NCHW |
// [8388609] perplexity | [8388610..) encodings [131072, 512]
// ---------------------------------------------------------------------------
extern "C" void kernel_launch(void* const* d_in, const int* in_sizes, int n_in,
                              void* d_out, int out_size)
{
    const float* inputs = (const float*)d_in[0];
    const float* emb_w  = (const float*)d_in[1];
    const float* ema_cs = (const float*)d_in[2];
    const float* ema_w  = (const float*)d_in[3];
    float* out  = (float*)d_out;
    float* outQ = out + 1;
    float* outP = out + 1 + 8388608;
    float* outE = out + 2 + 8388608;

    cudaFuncSetAttribute(k_main, cudaFuncAttributeMaxDynamicSharedMemorySize, SMEM_DYN);

    k_init<<<64, 512>>>(emb_w);
    k_main<<<NROWS / 128, 256, SMEM_DYN>>>(inputs, outE);
    k_update_cs<<<1, 512>>>(ema_cs, outP);
    k_update_emb<<<64, 512>>>(ema_w);
    k_quant<<<NROWS / 64, 256>>>(inputs, outQ);
    k_final<<<1, 1>>>(out);
}

// round 6
// speedup vs baseline: 2.0316x; 1.0191x over previous
#include <cuda_runtime.h>
#include <cuda_fp16.h>
#include <math.h>
#include <stdint.h>

#define NROWS 131072
#define DDIM  64
#define KCODE 512

// ---- dynamic smem byte offsets for k_main ----
// planes padded to 72 halves (144 B) per row -> 4-bank shift per row/col
#define OFF_AH  0           // 128 rows x 144B
#define OFF_AL  18432
#define OFF_BH  36864       // 128 codes x 144B (one chunk)
#define OFF_BL  55296
#define OFF_EN  73728       // float[512]
#define OFF_XN  75776       // float[128]
#define OFF_IDX 76288       // int[128]
#define SMEM_DYN 76800

// ---- static device scratch ----
__device__ __align__(16) __half g_Bh[KCODE * DDIM];   // codebook hi plane
__device__ __align__(16) __half g_Bl[KCODE * DDIM];   // codebook lo' plane
__device__ float  g_enorm[KCODE];
__device__ float  g_dw[KCODE * DDIM];
__device__ int    g_counts[KCODE];
__device__ float  g_csS[KCODE];
__device__ float  g_new_emb[KCODE * DDIM];
__device__ int    g_idx[NROWS];
__device__ float  g_loss;

// ---- helpers ----
__device__ __forceinline__ uint32_t smem_u32(const void* p) {
    uint32_t a;
    asm("{ .reg .u64 t; cvta.to.shared.u64 t, %1; cvt.u32.u64 %0, t; }"
        : "=r"(a) : "l"(p));
    return a;
}
__device__ __forceinline__ void split2h(float a, __half& hi, __half& lo) {
    hi = __float2half_rn(a);
    float r = a - __half2float(hi);      // exact
    lo = __float2half_rn(r * 2048.0f);   // scaled residual, avoids subnormals
}
__device__ __forceinline__ void mma16(float c[4], const uint32_t a[4],
                                      uint32_t b0, uint32_t b1) {
    asm volatile("mma.sync.aligned.m16n8k16.row.col.f32.f16.f16.f32 "
                 "{%0,%1,%2,%3}, {%4,%5,%6,%7}, {%8,%9}, {%0,%1,%2,%3};"
                 : "+f"(c[0]), "+f"(c[1]), "+f"(c[2]), "+f"(c[3])
                 : "r"(a[0]), "r"(a[1]), "r"(a[2]), "r"(a[3]),
                   "r"(b0), "r"(b1));
}
__device__ __forceinline__ void ldsm4(uint32_t& r0, uint32_t& r1,
                                      uint32_t& r2, uint32_t& r3, uint32_t addr) {
    asm volatile("ldmatrix.sync.aligned.m8n8.x4.shared.b16 {%0,%1,%2,%3}, [%4];"
                 : "=r"(r0), "=r"(r1), "=r"(r2), "=r"(r3) : "r"(addr));
}

// ---------------------------------------------------------------------------
// k_zero: zero dw / counts. grid 64 x 512.
// ---------------------------------------------------------------------------
__global__ void k_zero()
{
    const int gid = blockIdx.x * 512 + threadIdx.x;
    g_dw[gid] = 0.0f;
    if (blockIdx.x == 0) g_counts[threadIdx.x] = 0;
}

// ---------------------------------------------------------------------------
// k_split: codebook fp32 -> fp16 (hi, lo') planes + norms. grid 64 x 512.
// ---------------------------------------------------------------------------
__global__ void k_split(const float* __restrict__ emb)
{
    const int t = threadIdx.x;
    const int gid = blockIdx.x * 512 + t;
    float a = emb[gid];
    __half hi, lo;
    split2h(a, hi, lo);
    g_Bh[gid] = hi;
    g_Bl[gid] = lo;
    if (blockIdx.x == 0) {
        const float4* e4 = (const float4*)(emb + t * DDIM);
        float s = 0.0f;
#pragma unroll
        for (int i = 0; i < 16; i++) {
            float4 v = e4[i];
            s += v.x * v.x + v.y * v.y + v.z * v.z + v.w * v.w;
        }
        g_enorm[t] = s;
    }
}

// k_zero_loss: tiny 3rd launch (also positions k_main as launch #4 for ncu)
__global__ void k_zero_loss() { g_loss = 0.0f; }

// ---------------------------------------------------------------------------
// k_main: double-fp16 m16n8k16 distances + argmin + fused one-hot + dw.
// grid 1024 x 256, 2 blocks/SM. Block tile: 128 rows x 512 codes, K = 64.
// Warp w owns rows w*16 .. w*16+15. B fragments via ldmatrix.x4.
// ---------------------------------------------------------------------------
__global__ void __launch_bounds__(256, 2) k_main(const float* __restrict__ flat,
                                                 float* __restrict__ enc)
{
    extern __shared__ __align__(16) unsigned char smx[];
    float* sEn  = (float*)(smx + OFF_EN);
    float* sXn  = (float*)(smx + OFF_XN);
    int*   sIdx = (int*)(smx + OFF_IDX);

    const int tid  = threadIdx.x;
    const int lane = tid & 31;
    const int w    = tid >> 5;
    const int n0   = blockIdx.x * 128;
    const uint32_t sbase = smem_u32(smx);

    // ---- A fill: fp32 -> (hi, lo') fp16 planes; row norms ----
    {
        const float2* f2 = (const float2*)(flat + (size_t)n0 * DDIM);
#pragma unroll
        for (int it = 0; it < 16; it++) {
            int i = it * 256 + tid;          // 4096 half2-slots (128 rows x 32)
            int row = i >> 5, j = i & 31;
            float2 a = f2[i];
            __half hx, lx, hy, ly;
            split2h(a.x, hx, lx);
            split2h(a.y, hy, ly);
            __half2 h; h.x = hx; h.y = hy;
            *(__half2*)(smx + OFF_AH + row * 144 + j * 4) = h;
            h.x = lx; h.y = ly;
            *(__half2*)(smx + OFF_AL + row * 144 + j * 4) = h;
            float sq = fmaf(a.x, a.x, a.y * a.y);
#pragma unroll
            for (int o = 16; o; o >>= 1) sq += __shfl_xor_sync(0xffffffffu, sq, o);
            if (lane == 0) sXn[row] = sq;    // row == it*8 + w for this warp
        }
    }
    for (int i = tid; i < KCODE; i += 256) sEn[i] = g_enorm[i];
    __syncthreads();

    // ---- A fragment preload (register-resident): 4 k-steps of 16 ----
    const int r0 = w * 16 + (lane >> 2);
    uint32_t ah[4][4], al[4][4];
#pragma unroll
    for (int ks = 0; ks < 4; ks++) {
        int kb2 = (ks * 16 + (lane & 3) * 2) * 2;   // byte offset within row
        ah[ks][0] = *(const uint32_t*)(smx + OFF_AH + r0 * 144 + kb2);
        ah[ks][1] = *(const uint32_t*)(smx + OFF_AH + (r0 + 8) * 144 + kb2);
        ah[ks][2] = *(const uint32_t*)(smx + OFF_AH + r0 * 144 + kb2 + 16);
        ah[ks][3] = *(const uint32_t*)(smx + OFF_AH + (r0 + 8) * 144 + kb2 + 16);
        al[ks][0] = *(const uint32_t*)(smx + OFF_AL + r0 * 144 + kb2);
        al[ks][1] = *(const uint32_t*)(smx + OFF_AL + (r0 + 8) * 144 + kb2);
        al[ks][2] = *(const uint32_t*)(smx + OFF_AL + r0 * 144 + kb2 + 16);
        al[ks][3] = *(const uint32_t*)(smx + OFF_AL + (r0 + 8) * 144 + kb2 + 16);
    }
    const float xn0 = sXn[r0];
    const float xn1 = sXn[r0 + 8];
    float mn0 = 3.402823466e38f, mn1 = 3.402823466e38f;
    int   mi0 = 0, mi1 = 0;

    const float C1 = 4.8828125e-4f;          // 2^-11
    const float C2 = 2.384185791015625e-7f;  // 2^-22

    // per-thread ldmatrix base: code row = lane&7 (stride 144B), kseg = lane>>3
    const uint32_t lmOff = (uint32_t)((lane & 7) * 144 + (lane >> 3) * 16);
    const uint32_t bHbase = sbase + OFF_BH + lmOff;
    const uint32_t bLbase = sbase + OFF_BL + lmOff;

    // ---- main loop: 4 chunks of 128 codes ----
#pragma unroll 1
    for (int c = 0; c < 4; c++) {
        // B chunk fill: 8B copies, padded stride 144B
        {
            const uint2* sh = (const uint2*)(g_Bh + (size_t)c * 128 * 64);
            const uint2* sl = (const uint2*)(g_Bl + (size_t)c * 128 * 64);
#pragma unroll
            for (int it = 0; it < 8; it++) {
                int i = it * 256 + tid;       // 2048 x 8B per plane
                int code = i >> 4, j = i & 15;
                *(uint2*)(smx + OFF_BH + code * 144 + j * 8) = sh[i];
                *(uint2*)(smx + OFF_BL + code * 144 + j * 8) = sl[i];
            }
        }
        __syncthreads();

#pragma unroll
        for (int pr = 0; pr < 8; pr++) {      // 16 codes per pr
#pragma unroll
            for (int t2 = 0; t2 < 2; t2++) {
                const uint32_t cOff = (uint32_t)((pr * 16 + t2 * 8) * 144);
                // B fragments: 2 LDSM.x4 per plane cover ks0..3
                uint32_t bh[4][2], bl[4][2];
                ldsm4(bh[0][0], bh[0][1], bh[1][0], bh[1][1], bHbase + cOff);
                ldsm4(bh[2][0], bh[2][1], bh[3][0], bh[3][1], bHbase + cOff + 64);
                ldsm4(bl[0][0], bl[0][1], bl[1][0], bl[1][1], bLbase + cOff);
                ldsm4(bl[2][0], bl[2][1], bl[3][0], bl[3][1], bLbase + cOff + 64);

                float hh[4], mm[4], ll[4];
#pragma unroll
                for (int i = 0; i < 4; i++) { hh[i] = 0.0f; mm[i] = 0.0f; ll[i] = 0.0f; }
#pragma unroll
                for (int ks = 0; ks < 4; ks++) {
                    mma16(hh, ah[ks], bh[ks][0], bh[ks][1]);   // hi*hi   (1)
                    mma16(mm, ah[ks], bl[ks][0], bl[ks][1]);   // hi*lo'  (2^-11)
                    mma16(mm, al[ks], bh[ks][0], bh[ks][1]);   // lo'*hi  (2^-11)
                    mma16(ll, al[ks], bl[ks][0], bl[ks][1]);   // lo'*lo' (2^-22)
                }

                // epilogue: fold into running argmin (ascending col per row)
                const int cb = c * 128 + pr * 16 + t2 * 8 + (lane & 3) * 2;
#pragma unroll
                for (int i = 0; i < 4; i++) {
                    float dot = fmaf(C2, ll[i], fmaf(C1, mm[i], hh[i]));
                    int col = cb + (i & 1);
                    float xn = (i < 2) ? xn0 : xn1;
                    float s = __fadd_rn(__fsub_rn(xn, __fmul_rn(2.0f, dot)), sEn[col]);
                    if (i < 2) { if (s < mn0) { mn0 = s; mi0 = col; } }
                    else       { if (s < mn1) { mn1 = s; mi1 = col; } }
                }
            }
        }
        __syncthreads();   // done reading this B chunk
    }

    // ---- cross-lane argmin reduce (4 threads share each row) ----
#pragma unroll
    for (int off = 1; off < 4; off <<= 1) {
        float om = __shfl_xor_sync(0xffffffffu, mn0, off);
        int   oi = __shfl_xor_sync(0xffffffffu, mi0, off);
        if (om < mn0 || (om == mn0 && oi < mi0)) { mn0 = om; mi0 = oi; }
        om = __shfl_xor_sync(0xffffffffu, mn1, off);
        oi = __shfl_xor_sync(0xffffffffu, mi1, off);
        if (om < mn1 || (om == mn1 && oi < mi1)) { mn1 = om; mi1 = oi; }
    }
    if ((lane & 3) == 0) {
        g_idx[n0 + r0] = mi0;     sIdx[r0] = mi0;
        g_idx[n0 + r0 + 8] = mi1; sIdx[r0 + 8] = mi1;
        atomicAdd(&g_counts[mi0], 1);
        atomicAdd(&g_counts[mi1], 1);
    }
    __syncthreads();

    // ---- fused encodings write: zeros + one-hot (float2: base 8B-aligned) ----
    {
        float2* eb = (float2*)(enc + (size_t)n0 * KCODE);
#pragma unroll 4
        for (int it = 0; it < 128; it++) {
            int i = it * 256 + tid;          // 32768 float2 = 128 rows x 256
            int row = i >> 8, f = i & 255;
            int hot = sIdx[row];
            int base = f << 1;
            float2 v;
            v.x = (hot == base)     ? 1.0f : 0.0f;
            v.y = (hot == base + 1) ? 1.0f : 0.0f;
            eb[i] = v;
        }
    }

    // ---- dw segment-sum scatter (coalesced reads, fp atomics) ----
    {
        const float* rowsG = flat + (size_t)n0 * DDIM;
#pragma unroll 4
        for (int it = 0; it < 32; it++) {
            int i = it * 256 + tid;          // 8192 elements
            int r = i >> 6, d = i & 63;
            atomicAdd(&g_dw[sIdx[r] * DDIM + d], rowsG[i]);
        }
    }
}

// ---------------------------------------------------------------------------
// k_update_cs: counts -> smoothed cluster sizes + perplexity. 1 x 512.
// ---------------------------------------------------------------------------
__global__ void k_update_cs(const float* __restrict__ ema_cs, float* __restrict__ outP)
{
    __shared__ float red[512];
    const int t = threadIdx.x;
    float c  = (float)g_counts[t];
    float cs = ema_cs[t] * 0.99f + 0.01f * c;
    red[t] = cs;
    __syncthreads();
    for (int s = 256; s; s >>= 1) { if (t < s) red[t] += red[t + s]; __syncthreads(); }
    float nsum = red[0];
    __syncthreads();
    g_csS[t] = (cs + 1e-5f) / (nsum + 512.0f * 1e-5f) * nsum;

    float p = c * (1.0f / 131072.0f);
    red[t] = p * logf(p + 1e-10f);
    __syncthreads();
    for (int s = 256; s; s >>= 1) { if (t < s) red[t] += red[t + s]; __syncthreads(); }
    if (t == 0) outP[0] = expf(-red[0]);
}

// k_update_emb: parallel codebook update. grid 64 x 512.
__global__ void k_update_emb(const float* __restrict__ ema_w)
{
    const int gid = blockIdx.x * 512 + threadIdx.x;  // 32768
    const int k = gid >> 6;
    float w = ema_w[gid] * 0.99f + 0.01f * g_dw[gid];
    g_new_emb[gid] = w / g_csS[k];
}

// ---------------------------------------------------------------------------
// k_quant: gather updated codebook, NHWC->NCHW write, loss partial.
// grid NROWS/64 x 256
// ---------------------------------------------------------------------------
__global__ __launch_bounds__(256) void k_quant(const float* __restrict__ x,
                                               float* __restrict__ outQ)
{
    __shared__ float q[64][65];
    __shared__ int   idxs[64];
    __shared__ float wsum[8];
    const int t  = threadIdx.x;
    const int n0 = blockIdx.x * 64;
    if (t < 64) idxs[t] = g_idx[n0 + t];
    __syncthreads();

    float lsum = 0.0f;
    const float* xb = x + (size_t)n0 * DDIM;
#pragma unroll
    for (int it = 0; it < 16; it++) {
        int i = it * 256 + t;
        int r = i >> 6, d = i & 63;
        float qv = g_new_emb[idxs[r] * DDIM + d];
        float xv = xb[i];
        float df = qv - xv;
        lsum = fmaf(df, df, lsum);
        q[r][d] = qv;
    }
    __syncthreads();

    const int b   = n0 >> 12;
    const int loc = n0 & 4095;
    float* dst = outQ + (size_t)b * 262144 + loc;
#pragma unroll
    for (int it = 0; it < 16; it++) {
        int i = it * 256 + t;
        int d = i >> 6, n = i & 63;
        dst[d * 4096 + n] = q[n][d];
    }

#pragma unroll
    for (int o = 16; o; o >>= 1) lsum += __shfl_xor_sync(0xffffffffu, lsum, o);
    if ((t & 31) == 0) wsum[t >> 5] = lsum;
    __syncthreads();
    if (t == 0) {
        float s = 0.0f;
#pragma unroll
        for (int wv = 0; wv < 8; wv++) s += wsum[wv];
        atomicAdd(&g_loss, s);
    }
}

__global__ void k_final(float* __restrict__ out0)
{
    out0[0] = 0.25f * g_loss * (1.0f / 8388608.0f);
}

// ---------------------------------------------------------------------------
// Output layout (float32): [0] loss | [1..8388609) quantized NCHW |
// [8388609] perplexity | [8388610..) encodings [131072, 512]
// ---------------------------------------------------------------------------
extern "C" void kernel_launch(void* const* d_in, const int* in_sizes, int n_in,
                              void* d_out, int out_size)
{
    const float* inputs = (const float*)d_in[0];
    const float* emb_w  = (const float*)d_in[1];
    const float* ema_cs = (const float*)d_in[2];
    const float* ema_w  = (const float*)d_in[3];
    float* out  = (float*)d_out;
    float* outQ = out + 1;
    float* outP = out + 1 + 8388608;
    float* outE = out + 2 + 8388608;

    cudaFuncSetAttribute(k_main, cudaFuncAttributeMaxDynamicSharedMemorySize, SMEM_DYN);

    k_zero<<<64, 512>>>();                 // launch 1
    k_split<<<64, 512>>>(emb_w);           // launch 2
    k_zero_loss<<<1, 1>>>();               // launch 3
    k_main<<<NROWS / 128, 256, SMEM_DYN>>>(inputs, outE);   // launch 4 (ncu target)
    k_update_cs<<<1, 512>>>(ema_cs, outP);
    k_update_emb<<<64, 512>>>(ema_w);
    k_quant<<<NROWS / 64, 256>>>(inputs, outQ);
    k_final<<<1, 1>>>(out);
}

// round 7
// speedup vs baseline: 2.1079x; 1.0376x over previous
#include <cuda_runtime.h>
#include <cuda_fp16.h>
#include <math.h>
#include <stdint.h>

#define NROWS 131072
#define DDIM  64
#define KCODE 512

// ---- dynamic smem byte offsets for k_main ----
// planes padded to 72 halves (144 B) per row -> 4-bank shift per row/col
#define OFF_AH  0           // 128 rows x 144B
#define OFF_AL  18432
#define OFF_BH  36864       // 128 codes x 144B (one chunk)
#define OFF_BL  55296
#define OFF_EN  73728       // float[512] (0.5*||e||^2)
#define OFF_IDX 75776       // int[128]
#define SMEM_DYN 76288

// ---- static device scratch ----
__device__ __align__(16) __half g_Bh[KCODE * DDIM];   // codebook hi plane
__device__ __align__(16) __half g_Bl[KCODE * DDIM];   // codebook lo' plane
__device__ float  g_en2[KCODE];                       // 0.5*||e||^2
__device__ float  g_dw[KCODE * DDIM];
__device__ int    g_counts[KCODE];
__device__ float  g_csS[KCODE];
__device__ float  g_new_emb[KCODE * DDIM];
__device__ int    g_idx[NROWS];
__device__ float  g_loss;

// ---- helpers ----
__device__ __forceinline__ uint32_t smem_u32(const void* p) {
    uint32_t a;
    asm("{ .reg .u64 t; cvta.to.shared.u64 t, %1; cvt.u32.u64 %0, t; }"
        : "=r"(a) : "l"(p));
    return a;
}
__device__ __forceinline__ void split2h(float a, __half& hi, __half& lo) {
    hi = __float2half_rn(a);
    float r = a - __half2float(hi);      // exact
    lo = __float2half_rn(r * 2048.0f);   // scaled residual, avoids subnormals
}
__device__ __forceinline__ void mma16(float c[4], const uint32_t a[4],
                                      uint32_t b0, uint32_t b1) {
    asm volatile("mma.sync.aligned.m16n8k16.row.col.f32.f16.f16.f32 "
                 "{%0,%1,%2,%3}, {%4,%5,%6,%7}, {%8,%9}, {%0,%1,%2,%3};"
                 : "+f"(c[0]), "+f"(c[1]), "+f"(c[2]), "+f"(c[3])
                 : "r"(a[0]), "r"(a[1]), "r"(a[2]), "r"(a[3]),
                   "r"(b0), "r"(b1));
}
__device__ __forceinline__ void ldsm4(uint32_t& r0, uint32_t& r1,
                                      uint32_t& r2, uint32_t& r3, uint32_t addr) {
    asm volatile("ldmatrix.sync.aligned.m8n8.x4.shared.b16 {%0,%1,%2,%3}, [%4];"
                 : "=r"(r0), "=r"(r1), "=r"(r2), "=r"(r3) : "r"(addr));
}

// ---------------------------------------------------------------------------
// k_zero: zero dw / counts. grid 64 x 512.
// ---------------------------------------------------------------------------
__global__ void k_zero()
{
    const int gid = blockIdx.x * 512 + threadIdx.x;
    g_dw[gid] = 0.0f;
    if (blockIdx.x == 0) g_counts[threadIdx.x] = 0;
}

// ---------------------------------------------------------------------------
// k_split: codebook fp32 -> fp16 (hi, lo') planes + half-norms. grid 64 x 512.
// ---------------------------------------------------------------------------
__global__ void k_split(const float* __restrict__ emb)
{
    const int t = threadIdx.x;
    const int gid = blockIdx.x * 512 + t;
    float a = emb[gid];
    __half hi, lo;
    split2h(a, hi, lo);
    g_Bh[gid] = hi;
    g_Bl[gid] = lo;
    if (blockIdx.x == 0) {
        const float4* e4 = (const float4*)(emb + t * DDIM);
        float s = 0.0f;
#pragma unroll
        for (int i = 0; i < 16; i++) {
            float4 v = e4[i];
            s += v.x * v.x + v.y * v.y + v.z * v.z + v.w * v.w;
        }
        g_en2[t] = 0.5f * s;
    }
}

// k_zero_loss: tiny 3rd launch (positions k_main as launch #4 for ncu)
__global__ void k_zero_loss() { g_loss = 0.0f; }

// ---------------------------------------------------------------------------
// k_main: 3-product double-fp16 m16n8k16 + argmin + fused one-hot + dw.
// grid 1024 x 256, 2 blocks/SM. Block tile: 128 rows x 512 codes, K = 64.
// Warp w owns rows w*16 .. w*16+15. B fragments via ldmatrix.x4.
// argmin over s = 0.5*||e||^2 - dot   (monotone transform of reference score)
// ---------------------------------------------------------------------------
__global__ void __launch_bounds__(256, 2) k_main(const float* __restrict__ flat,
                                                 float* __restrict__ enc)
{
    extern __shared__ __align__(16) unsigned char smx[];
    float* sEn2 = (float*)(smx + OFF_EN);
    int*   sIdx = (int*)(smx + OFF_IDX);

    const int tid  = threadIdx.x;
    const int lane = tid & 31;
    const int w    = tid >> 5;
    const int n0   = blockIdx.x * 128;
    const uint32_t sbase = smem_u32(smx);

    // ---- A fill: fp32 -> (hi, lo') fp16 planes ----
    {
        const float2* f2 = (const float2*)(flat + (size_t)n0 * DDIM);
#pragma unroll
        for (int it = 0; it < 16; it++) {
            int i = it * 256 + tid;          // 4096 half2-slots (128 rows x 32)
            int row = i >> 5, j = i & 31;
            float2 a = f2[i];
            __half hx, lx, hy, ly;
            split2h(a.x, hx, lx);
            split2h(a.y, hy, ly);
            __half2 h; h.x = hx; h.y = hy;
            *(__half2*)(smx + OFF_AH + row * 144 + j * 4) = h;
            h.x = lx; h.y = ly;
            *(__half2*)(smx + OFF_AL + row * 144 + j * 4) = h;
        }
    }
    for (int i = tid; i < KCODE; i += 256) sEn2[i] = g_en2[i];
    __syncthreads();

    // ---- A fragment preload (register-resident): 4 k-steps of 16 ----
    const int r0 = w * 16 + (lane >> 2);
    uint32_t ah[4][4], al[4][4];
#pragma unroll
    for (int ks = 0; ks < 4; ks++) {
        int kb2 = (ks * 16 + (lane & 3) * 2) * 2;   // byte offset within row
        ah[ks][0] = *(const uint32_t*)(smx + OFF_AH + r0 * 144 + kb2);
        ah[ks][1] = *(const uint32_t*)(smx + OFF_AH + (r0 + 8) * 144 + kb2);
        ah[ks][2] = *(const uint32_t*)(smx + OFF_AH + r0 * 144 + kb2 + 16);
        ah[ks][3] = *(const uint32_t*)(smx + OFF_AH + (r0 + 8) * 144 + kb2 + 16);
        al[ks][0] = *(const uint32_t*)(smx + OFF_AL + r0 * 144 + kb2);
        al[ks][1] = *(const uint32_t*)(smx + OFF_AL + (r0 + 8) * 144 + kb2);
        al[ks][2] = *(const uint32_t*)(smx + OFF_AL + r0 * 144 + kb2 + 16);
        al[ks][3] = *(const uint32_t*)(smx + OFF_AL + (r0 + 8) * 144 + kb2 + 16);
    }
    float mn0 = 3.402823466e38f, mn1 = 3.402823466e38f;
    int   mi0 = 0, mi1 = 0;

    const float C1 = 4.8828125e-4f;          // 2^-11

    // per-thread ldmatrix base: code row = lane&7 (stride 144B), kseg = lane>>3
    const uint32_t lmOff = (uint32_t)((lane & 7) * 144 + (lane >> 3) * 16);
    const uint32_t bHbase = sbase + OFF_BH + lmOff;
    const uint32_t bLbase = sbase + OFF_BL + lmOff;

    // ---- main loop: 4 chunks of 128 codes ----
#pragma unroll 1
    for (int c = 0; c < 4; c++) {
        // B chunk fill: 8B copies, padded stride 144B
        {
            const uint2* sh = (const uint2*)(g_Bh + (size_t)c * 128 * 64);
            const uint2* sl = (const uint2*)(g_Bl + (size_t)c * 128 * 64);
#pragma unroll
            for (int it = 0; it < 8; it++) {
                int i = it * 256 + tid;       // 2048 x 8B per plane
                int code = i >> 4, j = i & 15;
                *(uint2*)(smx + OFF_BH + code * 144 + j * 8) = sh[i];
                *(uint2*)(smx + OFF_BL + code * 144 + j * 8) = sl[i];
            }
        }
        __syncthreads();

#pragma unroll
        for (int pr = 0; pr < 8; pr++) {      // 16 codes per pr
#pragma unroll
            for (int t2 = 0; t2 < 2; t2++) {
                const uint32_t cOff = (uint32_t)((pr * 16 + t2 * 8) * 144);
                // B fragments: 2 LDSM.x4 per plane cover ks0..3
                uint32_t bh[4][2], bl[4][2];
                ldsm4(bh[0][0], bh[0][1], bh[1][0], bh[1][1], bHbase + cOff);
                ldsm4(bh[2][0], bh[2][1], bh[3][0], bh[3][1], bHbase + cOff + 64);
                ldsm4(bl[0][0], bl[0][1], bl[1][0], bl[1][1], bLbase + cOff);
                ldsm4(bl[2][0], bl[2][1], bl[3][0], bl[3][1], bLbase + cOff + 64);

                float hh[4], m0[4], m1[4];
#pragma unroll
                for (int i = 0; i < 4; i++) { hh[i] = 0.0f; m0[i] = 0.0f; m1[i] = 0.0f; }
#pragma unroll
                for (int ks = 0; ks < 4; ks++) {
                    mma16(hh, ah[ks], bh[ks][0], bh[ks][1]);   // hi*hi   (1)
                    mma16(m0, ah[ks], bl[ks][0], bl[ks][1]);   // hi*lo'  (2^-11)
                    mma16(m1, al[ks], bh[ks][0], bh[ks][1]);   // lo'*hi  (2^-11)
                }

                // epilogue: s = 0.5||e||^2 - dot ; fold into running argmin
                const int cb = c * 128 + pr * 16 + t2 * 8 + (lane & 3) * 2;
#pragma unroll
                for (int i = 0; i < 4; i++) {
                    float dot = fmaf(C1, m0[i] + m1[i], hh[i]);
                    int col = cb + (i & 1);
                    float s = __fsub_rn(sEn2[col], dot);
                    if (i < 2) { if (s < mn0) { mn0 = s; mi0 = col; } }
                    else       { if (s < mn1) { mn1 = s; mi1 = col; } }
                }
            }
        }
        __syncthreads();   // done reading this B chunk
    }

    // ---- cross-lane argmin reduce (4 threads share each row) ----
#pragma unroll
    for (int off = 1; off < 4; off <<= 1) {
        float om = __shfl_xor_sync(0xffffffffu, mn0, off);
        int   oi = __shfl_xor_sync(0xffffffffu, mi0, off);
        if (om < mn0 || (om == mn0 && oi < mi0)) { mn0 = om; mi0 = oi; }
        om = __shfl_xor_sync(0xffffffffu, mn1, off);
        oi = __shfl_xor_sync(0xffffffffu, mi1, off);
        if (om < mn1 || (om == mn1 && oi < mi1)) { mn1 = om; mi1 = oi; }
    }
    if ((lane & 3) == 0) {
        g_idx[n0 + r0] = mi0;     sIdx[r0] = mi0;
        g_idx[n0 + r0 + 8] = mi1; sIdx[r0 + 8] = mi1;
        atomicAdd(&g_counts[mi0], 1);
        atomicAdd(&g_counts[mi1], 1);
    }

    // ---- encodings: stream zeros, then scatter the ones ----
    {
        float2* eb = (float2*)(enc + (size_t)n0 * KCODE);
        const float2 z = make_float2(0.0f, 0.0f);
#pragma unroll 8
        for (int it = 0; it < 128; it++)
            eb[it * 256 + tid] = z;          // 32768 float2 = 128 rows x 512
    }
    __syncthreads();
    if (tid < 128)
        enc[(size_t)(n0 + tid) * KCODE + sIdx[tid]] = 1.0f;

    // ---- dw segment-sum scatter (coalesced reads, fp atomics) ----
    {
        const float* rowsG = flat + (size_t)n0 * DDIM;
#pragma unroll 4
        for (int it = 0; it < 32; it++) {
            int i = it * 256 + tid;          // 8192 elements
            int r = i >> 6, d = i & 63;
            atomicAdd(&g_dw[sIdx[r] * DDIM + d], rowsG[i]);
        }
    }
}

// ---------------------------------------------------------------------------
// k_update_cs: counts -> smoothed cluster sizes + perplexity. 1 x 512.
// ---------------------------------------------------------------------------
__global__ void k_update_cs(const float* __restrict__ ema_cs, float* __restrict__ outP)
{
    __shared__ float red[512];
    const int t = threadIdx.x;
    float c  = (float)g_counts[t];
    float cs = ema_cs[t] * 0.99f + 0.01f * c;
    red[t] = cs;
    __syncthreads();
    for (int s = 256; s; s >>= 1) { if (t < s) red[t] += red[t + s]; __syncthreads(); }
    float nsum = red[0];
    __syncthreads();
    g_csS[t] = (cs + 1e-5f) / (nsum + 512.0f * 1e-5f) * nsum;

    float p = c * (1.0f / 131072.0f);
    red[t] = p * logf(p + 1e-10f);
    __syncthreads();
    for (int s = 256; s; s >>= 1) { if (t < s) red[t] += red[t + s]; __syncthreads(); }
    if (t == 0) outP[0] = expf(-red[0]);
}

// k_update_emb: parallel codebook update. grid 64 x 512.
__global__ void k_update_emb(const float* __restrict__ ema_w)
{
    const int gid = blockIdx.x * 512 + threadIdx.x;  // 32768
    const int k = gid >> 6;
    float w = ema_w[gid] * 0.99f + 0.01f * g_dw[gid];
    g_new_emb[gid] = w / g_csS[k];
}

// ---------------------------------------------------------------------------
// k_quant: gather updated codebook, NHWC->NCHW write, loss partial.
// grid NROWS/64 x 256
// ---------------------------------------------------------------------------
__global__ __launch_bounds__(256) void k_quant(const float* __restrict__ x,
                                               float* __restrict__ outQ)
{
    __shared__ float q[64][65];
    __shared__ int   idxs[64];
    __shared__ float wsum[8];
    const int t  = threadIdx.x;
    const int n0 = blockIdx.x * 64;
    if (t < 64) idxs[t] = g_idx[n0 + t];
    __syncthreads();

    float lsum = 0.0f;
    const float* xb = x + (size_t)n0 * DDIM;
#pragma unroll
    for (int it = 0; it < 16; it++) {
        int i = it * 256 + t;
        int r = i >> 6, d = i & 63;
        float qv = g_new_emb[idxs[r] * DDIM + d];
        float xv = xb[i];
        float df = qv - xv;
        lsum = fmaf(df, df, lsum);
        q[r][d] = qv;
    }
    __syncthreads();

    const int b   = n0 >> 12;
    const int loc = n0 & 4095;
    float* dst = outQ + (size_t)b * 262144 + loc;
#pragma unroll
    for (int it = 0; it < 16; it++) {
        int i = it * 256 + t;
        int d = i >> 6, n = i & 63;
        dst[d * 4096 + n] = q[n][d];
    }

#pragma unroll
    for (int o = 16; o; o >>= 1) lsum += __shfl_xor_sync(0xffffffffu, lsum, o);
    if ((t & 31) == 0) wsum[t >> 5] = lsum;
    __syncthreads();
    if (t == 0) {
        float s = 0.0f;
#pragma unroll
        for (int wv = 0; wv < 8; wv++) s += wsum[wv];
        atomicAdd(&g_loss, s);
    }
}

__global__ void k_final(float* __restrict__ out0)
{
    out0[0] = 0.25f * g_loss * (1.0f / 8388608.0f);
}

// ---------------------------------------------------------------------------
// Output layout (float32): [0] loss | [1..8388609) quantized NCHW |
// [8388609] perplexity | [8388610..) encodings [131072, 512]
// ---------------------------------------------------------------------------
extern "C" void kernel_launch(void* const* d_in, const int* in_sizes, int n_in,
                              void* d_out, int out_size)
{
    const float* inputs = (const float*)d_in[0];
    const float* emb_w  = (const float*)d_in[1];
    const float* ema_cs = (const float*)d_in[2];
    const float* ema_w  = (const float*)d_in[3];
    float* out  = (float*)d_out;
    float* outQ = out + 1;
    float* outP = out + 1 + 8388608;
    float* outE = out + 2 + 8388608;

    cudaFuncSetAttribute(k_main, cudaFuncAttributeMaxDynamicSharedMemorySize, SMEM_DYN);

    k_zero<<<64, 512>>>();                 // launch 1
    k_split<<<64, 512>>>(emb_w);           // launch 2
    k_zero_loss<<<1, 1>>>();               // launch 3
    k_main<<<NROWS / 128, 256, SMEM_DYN>>>(inputs, outE);   // launch 4 (ncu target)
    k_update_cs<<<1, 512>>>(ema_cs, outP);
    k_update_emb<<<64, 512>>>(ema_w);
    k_quant<<<NROWS / 64, 256>>>(inputs, outQ);
    k_final<<<1, 1>>>(out);
}

// round 8
// speedup vs baseline: 2.1923x; 1.0401x over previous
#include <cuda_runtime.h>
#include <cuda_fp16.h>
#include <math.h>
#include <stdint.h>

#define NROWS 131072
#define DDIM  64
#define KCODE 512

// ---- dynamic smem byte offsets for k_main ----
// planes padded to 72 halves (144 B) per row -> 4-bank shift per row/col
#define OFF_AH  0           // 128 rows x 144B
#define OFF_AL  18432
#define OFF_BH  36864       // 128 codes x 144B (one chunk)
#define OFF_BL  55296
#define OFF_EN  73728       // float[512] (0.5*||e||^2)
#define OFF_IDX 75776       // int[128]
#define SMEM_DYN 76288      // 3 blocks x 76288 = 228864 <= 232448 B/SM

// ---- static device scratch ----
__device__ __align__(16) __half g_Bh[KCODE * DDIM];   // codebook hi plane
__device__ __align__(16) __half g_Bl[KCODE * DDIM];   // codebook lo' plane
__device__ float  g_en2[KCODE];                       // 0.5*||e||^2
__device__ float  g_dw[KCODE * DDIM];
__device__ int    g_counts[KCODE];
__device__ float  g_csS[KCODE];
__device__ float  g_new_emb[KCODE * DDIM];
__device__ int    g_idx[NROWS];
__device__ float  g_loss;

// ---- helpers ----
__device__ __forceinline__ uint32_t smem_u32(const void* p) {
    uint32_t a;
    asm("{ .reg .u64 t; cvta.to.shared.u64 t, %1; cvt.u32.u64 %0, t; }"
        : "=r"(a) : "l"(p));
    return a;
}
__device__ __forceinline__ void split2h(float a, __half& hi, __half& lo) {
    hi = __float2half_rn(a);
    float r = a - __half2float(hi);      // exact
    lo = __float2half_rn(r * 2048.0f);   // scaled residual, avoids subnormals
}
__device__ __forceinline__ void mma16(float c[4], const uint32_t a[4],
                                      uint32_t b0, uint32_t b1) {
    asm volatile("mma.sync.aligned.m16n8k16.row.col.f32.f16.f16.f32 "
                 "{%0,%1,%2,%3}, {%4,%5,%6,%7}, {%8,%9}, {%0,%1,%2,%3};"
                 : "+f"(c[0]), "+f"(c[1]), "+f"(c[2]), "+f"(c[3])
                 : "r"(a[0]), "r"(a[1]), "r"(a[2]), "r"(a[3]),
                   "r"(b0), "r"(b1));
}
__device__ __forceinline__ void ldsm4(uint32_t& r0, uint32_t& r1,
                                      uint32_t& r2, uint32_t& r3, uint32_t addr) {
    asm volatile("ldmatrix.sync.aligned.m8n8.x4.shared.b16 {%0,%1,%2,%3}, [%4];"
                 : "=r"(r0), "=r"(r1), "=r"(r2), "=r"(r3) : "r"(addr));
}

// ---------------------------------------------------------------------------
// k_zero: zero dw / counts. grid 64 x 512.
// ---------------------------------------------------------------------------
__global__ void k_zero()
{
    const int gid = blockIdx.x * 512 + threadIdx.x;
    g_dw[gid] = 0.0f;
    if (blockIdx.x == 0) g_counts[threadIdx.x] = 0;
}

// ---------------------------------------------------------------------------
// k_split: codebook fp32 -> fp16 (hi, lo') planes + half-norms. grid 64 x 512.
// ---------------------------------------------------------------------------
__global__ void k_split(const float* __restrict__ emb)
{
    const int t = threadIdx.x;
    const int gid = blockIdx.x * 512 + t;
    float a = emb[gid];
    __half hi, lo;
    split2h(a, hi, lo);
    g_Bh[gid] = hi;
    g_Bl[gid] = lo;
    if (blockIdx.x == 0) {
        const float4* e4 = (const float4*)(emb + t * DDIM);
        float s = 0.0f;
#pragma unroll
        for (int i = 0; i < 16; i++) {
            float4 v = e4[i];
            s += v.x * v.x + v.y * v.y + v.z * v.z + v.w * v.w;
        }
        g_en2[t] = 0.5f * s;
    }
}

// k_zero_loss: tiny 3rd launch (positions k_main as launch #4 for ncu)
__global__ void k_zero_loss() { g_loss = 0.0f; }

// ---------------------------------------------------------------------------
// k_main: 3-product double-fp16 m16n8k16 + argmin + fused one-hot + dw.
// grid 1024 x 256, 3 blocks/SM (reg-capped). Block: 128 rows x 512 codes.
// Warp w owns rows w*16 .. w*16+15. B fragments via ldmatrix.x4.
// argmin over s = 0.5*||e||^2 - dot   (monotone transform of reference score)
// ---------------------------------------------------------------------------
__global__ void __launch_bounds__(256, 3) k_main(const float* __restrict__ flat,
                                                 float* __restrict__ enc)
{
    extern __shared__ __align__(16) unsigned char smx[];
    float* sEn2 = (float*)(smx + OFF_EN);
    int*   sIdx = (int*)(smx + OFF_IDX);

    const int tid  = threadIdx.x;
    const int lane = tid & 31;
    const int w    = tid >> 5;
    const int n0   = blockIdx.x * 128;
    const uint32_t sbase = smem_u32(smx);

    // ---- A fill: fp32 -> (hi, lo') fp16 planes ----
    {
        const float2* f2 = (const float2*)(flat + (size_t)n0 * DDIM);
#pragma unroll
        for (int it = 0; it < 16; it++) {
            int i = it * 256 + tid;          // 4096 half2-slots (128 rows x 32)
            int row = i >> 5, j = i & 31;
            float2 a = f2[i];
            __half hx, lx, hy, ly;
            split2h(a.x, hx, lx);
            split2h(a.y, hy, ly);
            __half2 h; h.x = hx; h.y = hy;
            *(__half2*)(smx + OFF_AH + row * 144 + j * 4) = h;
            h.x = lx; h.y = ly;
            *(__half2*)(smx + OFF_AL + row * 144 + j * 4) = h;
        }
    }
    for (int i = tid; i < KCODE; i += 256) sEn2[i] = g_en2[i];
    __syncthreads();

    // ---- A fragment preload (register-resident): 4 k-steps of 16 ----
    const int r0 = w * 16 + (lane >> 2);
    uint32_t ah[4][4], al[4][4];
#pragma unroll
    for (int ks = 0; ks < 4; ks++) {
        int kb2 = (ks * 16 + (lane & 3) * 2) * 2;   // byte offset within row
        ah[ks][0] = *(const uint32_t*)(smx + OFF_AH + r0 * 144 + kb2);
        ah[ks][1] = *(const uint32_t*)(smx + OFF_AH + (r0 + 8) * 144 + kb2);
        ah[ks][2] = *(const uint32_t*)(smx + OFF_AH + r0 * 144 + kb2 + 16);
        ah[ks][3] = *(const uint32_t*)(smx + OFF_AH + (r0 + 8) * 144 + kb2 + 16);
        al[ks][0] = *(const uint32_t*)(smx + OFF_AL + r0 * 144 + kb2);
        al[ks][1] = *(const uint32_t*)(smx + OFF_AL + (r0 + 8) * 144 + kb2);
        al[ks][2] = *(const uint32_t*)(smx + OFF_AL + r0 * 144 + kb2 + 16);
        al[ks][3] = *(const uint32_t*)(smx + OFF_AL + (r0 + 8) * 144 + kb2 + 16);
    }
    float mn0 = 3.402823466e38f, mn1 = 3.402823466e38f;
    int   mi0 = 0, mi1 = 0;

    const float C1 = 4.8828125e-4f;          // 2^-11

    // per-thread ldmatrix base: code row = lane&7 (stride 144B), kseg = lane>>3
    const uint32_t lmOff = (uint32_t)((lane & 7) * 144 + (lane >> 3) * 16);
    const uint32_t bHbase = sbase + OFF_BH + lmOff;
    const uint32_t bLbase = sbase + OFF_BL + lmOff;

    // ---- main loop: 4 chunks of 128 codes ----
#pragma unroll 1
    for (int c = 0; c < 4; c++) {
        // B chunk fill: 8B copies, padded stride 144B
        {
            const uint2* sh = (const uint2*)(g_Bh + (size_t)c * 128 * 64);
            const uint2* sl = (const uint2*)(g_Bl + (size_t)c * 128 * 64);
#pragma unroll
            for (int it = 0; it < 8; it++) {
                int i = it * 256 + tid;       // 2048 x 8B per plane
                int code = i >> 4, j = i & 15;
                *(uint2*)(smx + OFF_BH + code * 144 + j * 8) = sh[i];
                *(uint2*)(smx + OFF_BL + code * 144 + j * 8) = sl[i];
            }
        }
        __syncthreads();

#pragma unroll
        for (int pr = 0; pr < 8; pr++) {      // 16 codes per pr
#pragma unroll
            for (int t2 = 0; t2 < 2; t2++) {
                const uint32_t cOff = (uint32_t)((pr * 16 + t2 * 8) * 144);
                // B fragments: 2 LDSM.x4 per plane cover ks0..3
                uint32_t bh[4][2], bl[4][2];
                ldsm4(bh[0][0], bh[0][1], bh[1][0], bh[1][1], bHbase + cOff);
                ldsm4(bh[2][0], bh[2][1], bh[3][0], bh[3][1], bHbase + cOff + 64);
                ldsm4(bl[0][0], bl[0][1], bl[1][0], bl[1][1], bLbase + cOff);
                ldsm4(bl[2][0], bl[2][1], bl[3][0], bl[3][1], bLbase + cOff + 64);

                float hh[4], m0[4], m1[4];
#pragma unroll
                for (int i = 0; i < 4; i++) { hh[i] = 0.0f; m0[i] = 0.0f; m1[i] = 0.0f; }
#pragma unroll
                for (int ks = 0; ks < 4; ks++) {
                    mma16(hh, ah[ks], bh[ks][0], bh[ks][1]);   // hi*hi   (1)
                    mma16(m0, ah[ks], bl[ks][0], bl[ks][1]);   // hi*lo'  (2^-11)
                    mma16(m1, al[ks], bh[ks][0], bh[ks][1]);   // lo'*hi  (2^-11)
                }

                // epilogue: s = 0.5||e||^2 - dot ; fold into running argmin
                const int cb = c * 128 + pr * 16 + t2 * 8 + (lane & 3) * 2;
#pragma unroll
                for (int i = 0; i < 4; i++) {
                    float dot = fmaf(C1, m0[i] + m1[i], hh[i]);
                    int col = cb + (i & 1);
                    float s = __fsub_rn(sEn2[col], dot);
                    if (i < 2) { if (s < mn0) { mn0 = s; mi0 = col; } }
                    else       { if (s < mn1) { mn1 = s; mi1 = col; } }
                }
            }
        }
        __syncthreads();   // done reading this B chunk
    }

    // ---- cross-lane argmin reduce (4 threads share each row) ----
#pragma unroll
    for (int off = 1; off < 4; off <<= 1) {
        float om = __shfl_xor_sync(0xffffffffu, mn0, off);
        int   oi = __shfl_xor_sync(0xffffffffu, mi0, off);
        if (om < mn0 || (om == mn0 && oi < mi0)) { mn0 = om; mi0 = oi; }
        om = __shfl_xor_sync(0xffffffffu, mn1, off);
        oi = __shfl_xor_sync(0xffffffffu, mi1, off);
        if (om < mn1 || (om == mn1 && oi < mi1)) { mn1 = om; mi1 = oi; }
    }
    if ((lane & 3) == 0) {
        g_idx[n0 + r0] = mi0;     sIdx[r0] = mi0;
        g_idx[n0 + r0 + 8] = mi1; sIdx[r0 + 8] = mi1;
        atomicAdd(&g_counts[mi0], 1);
        atomicAdd(&g_counts[mi1], 1);
    }

    // ---- encodings: stream zeros, then scatter the ones ----
    {
        float2* eb = (float2*)(enc + (size_t)n0 * KCODE);
        const float2 z = make_float2(0.0f, 0.0f);
#pragma unroll 8
        for (int it = 0; it < 128; it++)
            eb[it * 256 + tid] = z;          // 32768 float2 = 128 rows x 512
    }
    __syncthreads();
    if (tid < 128)
        enc[(size_t)(n0 + tid) * KCODE + sIdx[tid]] = 1.0f;

    // ---- dw segment-sum scatter (coalesced reads, fp atomics) ----
    {
        const float* rowsG = flat + (size_t)n0 * DDIM;
#pragma unroll 4
        for (int it = 0; it < 32; it++) {
            int i = it * 256 + tid;          // 8192 elements
            int r = i >> 6, d = i & 63;
            atomicAdd(&g_dw[sIdx[r] * DDIM + d], rowsG[i]);
        }
    }
}

// ---------------------------------------------------------------------------
// k_update_cs: counts -> smoothed cluster sizes + perplexity. 1 x 512.
// ---------------------------------------------------------------------------
__global__ void k_update_cs(const float* __restrict__ ema_cs, float* __restrict__ outP)
{
    __shared__ float red[512];
    const int t = threadIdx.x;
    float c  = (float)g_counts[t];
    float cs = ema_cs[t] * 0.99f + 0.01f * c;
    red[t] = cs;
    __syncthreads();
    for (int s = 256; s; s >>= 1) { if (t < s) red[t] += red[t + s]; __syncthreads(); }
    float nsum = red[0];
    __syncthreads();
    g_csS[t] = (cs + 1e-5f) / (nsum + 512.0f * 1e-5f) * nsum;

    float p = c * (1.0f / 131072.0f);
    red[t] = p * logf(p + 1e-10f);
    __syncthreads();
    for (int s = 256; s; s >>= 1) { if (t < s) red[t] += red[t + s]; __syncthreads(); }
    if (t == 0) outP[0] = expf(-red[0]);
}

// k_update_emb: parallel codebook update. grid 64 x 512.
__global__ void k_update_emb(const float* __restrict__ ema_w)
{
    const int gid = blockIdx.x * 512 + threadIdx.x;  // 32768
    const int k = gid >> 6;
    float w = ema_w[gid] * 0.99f + 0.01f * g_dw[gid];
    g_new_emb[gid] = w / g_csS[k];
}

// ---------------------------------------------------------------------------
// k_quant: gather updated codebook, NHWC->NCHW write, loss partial.
// grid NROWS/64 x 256
// ---------------------------------------------------------------------------
__global__ __launch_bounds__(256) void k_quant(const float* __restrict__ x,
                                               float* __restrict__ outQ)
{
    __shared__ float q[64][65];
    __shared__ int   idxs[64];
    __shared__ float wsum[8];
    const int t  = threadIdx.x;
    const int n0 = blockIdx.x * 64;
    if (t < 64) idxs[t] = g_idx[n0 + t];
    __syncthreads();

    float lsum = 0.0f;
    const float* xb = x + (size_t)n0 * DDIM;
#pragma unroll
    for (int it = 0; it < 16; it++) {
        int i = it * 256 + t;
        int r = i >> 6, d = i & 63;
        float qv = g_new_emb[idxs[r] * DDIM + d];
        float xv = xb[i];
        float df = qv - xv;
        lsum = fmaf(df, df, lsum);
        q[r][d] = qv;
    }
    __syncthreads();

    const int b   = n0 >> 12;
    const int loc = n0 & 4095;
    float* dst = outQ + (size_t)b * 262144 + loc;
#pragma unroll
    for (int it = 0; it < 16; it++) {
        int i = it * 256 + t;
        int d = i >> 6, n = i & 63;
        dst[d * 4096 + n] = q[n][d];
    }

#pragma unroll
    for (int o = 16; o; o >>= 1) lsum += __shfl_xor_sync(0xffffffffu, lsum, o);
    if ((t & 31) == 0) wsum[t >> 5] = lsum;
    __syncthreads();
    if (t == 0) {
        float s = 0.0f;
#pragma unroll
        for (int wv = 0; wv < 8; wv++) s += wsum[wv];
        atomicAdd(&g_loss, s);
    }
}

__global__ void k_final(float* __restrict__ out0)
{
    out0[0] = 0.25f * g_loss * (1.0f / 8388608.0f);
}

// ---------------------------------------------------------------------------
// Output layout (float32): [0] loss | [1..8388609) quantized NCHW |
// [8388609] perplexity | [8388610..) encodings [131072, 512]
// ---------------------------------------------------------------------------
extern "C" void kernel_launch(void* const* d_in, const int* in_sizes, int n_in,
                              void* d_out, int out_size)
{
    const float* inputs = (const float*)d_in[0];
    const float* emb_w  = (const float*)d_in[1];
    const float* ema_cs = (const float*)d_in[2];
    const float* ema_w  = (const float*)d_in[3];
    float* out  = (float*)d_out;
    float* outQ = out + 1;
    float* outP = out + 1 + 8388608;
    float* outE = out + 2 + 8388608;

    cudaFuncSetAttribute(k_main, cudaFuncAttributeMaxDynamicSharedMemorySize, SMEM_DYN);

    k_zero<<<64, 512>>>();                 // launch 1
    k_split<<<64, 512>>>(emb_w);           // launch 2
    k_zero_loss<<<1, 1>>>();               // launch 3
    k_main<<<NROWS / 128, 256, SMEM_DYN>>>(inputs, outE);   // launch 4 (ncu target)
    k_update_cs<<<1, 512>>>(ema_cs, outP);
    k_update_emb<<<64, 512>>>(ema_w);
    k_quant<<<NROWS / 64, 256>>>(inputs, outQ);
    k_final<<<1, 1>>>(out);
}